// round 1
// baseline (speedup 1.0000x reference)
#include <cuda_runtime.h>

#define N_NODES 100000
#define FEAT 64
#define HID 128
#define N_EDGES 1200000

// Scratch (device globals — no allocation allowed)
__device__ float g_agg1[N_NODES * FEAT];   // mean-agg input of layer 1 (pre-division)
__device__ float g_agg2[N_NODES * HID];    // mean-agg input of layer 2 (pre-division)
__device__ float g_h[N_NODES * HID];       // hidden activations
__device__ float g_deg[N_NODES];           // in-degree (float)

// ---------------------------------------------------------------------------
__global__ void zero_kernel(float* p, int n4) {
    int i = blockIdx.x * blockDim.x + threadIdx.x;
    if (i < n4) ((float4*)p)[i] = make_float4(0.f, 0.f, 0.f, 0.f);
}

// ---------------------------------------------------------------------------
// Scatter layer 1: one thread per (edge, 4-feature chunk). 16 chunks/edge.
__global__ void scatter1_kernel(const float* __restrict__ x,
                                const int* __restrict__ ei) {
    int idx = blockIdx.x * blockDim.x + threadIdx.x;
    if (idx >= N_EDGES * 16) return;
    int e = idx >> 4;
    int c = idx & 15;
    int src = ei[e];
    int dst = ei[N_EDGES + e];
    float4 v = ((const float4*)x)[src * 16 + c];
    float* a = g_agg1 + (size_t)dst * FEAT + c * 4;
    atomicAdd(a + 0, v.x);
    atomicAdd(a + 1, v.y);
    atomicAdd(a + 2, v.z);
    atomicAdd(a + 3, v.w);
    if (c == 0) atomicAdd(&g_deg[dst], 1.0f);
}

// Scatter layer 2: one thread per (edge, 4-feature chunk). 32 chunks/edge.
__global__ void scatter2_kernel(const int* __restrict__ ei) {
    int idx = blockIdx.x * blockDim.x + threadIdx.x;
    if (idx >= N_EDGES * 32) return;
    int e = idx >> 5;
    int c = idx & 31;
    int src = ei[e];
    int dst = ei[N_EDGES + e];
    float4 v = ((const float4*)g_h)[src * 32 + c];
    float* a = g_agg2 + (size_t)dst * HID + c * 4;
    atomicAdd(a + 0, v.x);
    atomicAdd(a + 1, v.y);
    atomicAdd(a + 2, v.z);
    atomicAdd(a + 3, v.w);
}

// ---------------------------------------------------------------------------
// Layer 1: h[n, t] = relu( sum_f W1l[t,f]*agg1n[f] + b1l[t] + sum_f W1r[t,f]*x[n,f] )
// blockDim = 128 (t = hidden unit). 40 nodes per block, grid = 2500.
// Weights in SMEM transposed [f*128 + t] (conflict-free). Double-buffered node vec.
#define L1_NPB 40
__global__ void layer1_kernel(const float* __restrict__ x,
                              const float* __restrict__ W1l,
                              const float* __restrict__ b1l,
                              const float* __restrict__ W1r) {
    extern __shared__ float sm[];
    float* sWl = sm;                 // 8192 floats  [f*128 + h]
    float* sWr = sm + 8192;          // 8192 floats
    float* sb  = sm + 16384;         // 128
    float* svb = sm + 16512;         // 2 * 128 (double buffer: [agg(64) | x(64)])

    int t = threadIdx.x;
    for (int i = t; i < HID * FEAT; i += 128) {
        int h = i >> 6, f = i & 63;
        sWl[f * HID + h] = W1l[i];
        sWr[f * HID + h] = W1r[i];
    }
    sb[t] = b1l[t];
    __syncthreads();

    int n0 = blockIdx.x * L1_NPB;
    for (int j = 0; j < L1_NPB; j++) {
        int n = n0 + j;
        float* sv = svb + (j & 1) * 128;
        float inv = 1.0f / fmaxf(g_deg[n], 1.0f);
        if (t < 64) sv[t] = g_agg1[n * FEAT + t] * inv;
        else        sv[t] = x[n * FEAT + (t - 64)];
        __syncthreads();

        float a0 = sb[t], a1 = 0.f, a2 = 0.f, a3 = 0.f;
        #pragma unroll
        for (int f = 0; f < 64; f += 4) {
            a0 = fmaf(sWl[(f + 0) * 128 + t], sv[f + 0], a0);
            a0 = fmaf(sWr[(f + 0) * 128 + t], sv[64 + f + 0], a0);
            a1 = fmaf(sWl[(f + 1) * 128 + t], sv[f + 1], a1);
            a1 = fmaf(sWr[(f + 1) * 128 + t], sv[64 + f + 1], a1);
            a2 = fmaf(sWl[(f + 2) * 128 + t], sv[f + 2], a2);
            a2 = fmaf(sWr[(f + 2) * 128 + t], sv[64 + f + 2], a2);
            a3 = fmaf(sWl[(f + 3) * 128 + t], sv[f + 3], a3);
            a3 = fmaf(sWr[(f + 3) * 128 + t], sv[64 + f + 3], a3);
        }
        g_h[(size_t)n * HID + t] = fmaxf((a0 + a1) + (a2 + a3), 0.0f);
        // no second sync: double buffer makes next write safe
    }
}

// ---------------------------------------------------------------------------
// Layer 2: out[n, o] = sum_f W2l[o,f]*agg2n[f] + b2l[o] + sum_f W2r[o,f]*h[n,f]
// blockDim = 256: o = t&63 (out feature), j = t>>6 (local node 0..3).
// 32 nodes per block (8 iters of 4), grid = 3125.
__global__ void layer2_kernel(const float* __restrict__ W2l,
                              const float* __restrict__ b2l,
                              const float* __restrict__ W2r,
                              float* __restrict__ out) {
    extern __shared__ float sm[];
    float* sWl = sm;                 // 8192 floats  [f*64 + o]
    float* sWr = sm + 8192;          // 8192
    float* sb  = sm + 16384;         // 64
    float* svb = sm + 16448;         // 2 * 1024 (double buffer: 4 nodes * [agg(128)|h(128)])

    int t = threadIdx.x;
    int o = t & 63;
    int j = t >> 6;
    for (int i = t; i < FEAT * HID; i += 256) {
        int oo = i >> 7, f = i & 127;
        sWl[f * 64 + oo] = W2l[i];
        sWr[f * 64 + oo] = W2r[i];
    }
    if (t < 64) sb[t] = b2l[t];
    __syncthreads();

    int n0 = blockIdx.x * 32;
    for (int it = 0; it < 8; it++) {
        float* sv = svb + (it & 1) * 1024;
        #pragma unroll
        for (int s = 0; s < 4; s++) {
            int k = t + s * 256;         // 0..1023
            int jj = k >> 8;
            int kk = k & 255;
            int n = n0 + it * 4 + jj;
            float val;
            if (kk < 128) val = g_agg2[(size_t)n * HID + kk] / fmaxf(g_deg[n], 1.0f);
            else          val = g_h[(size_t)n * HID + (kk - 128)];
            sv[k] = val;
        }
        __syncthreads();

        int n = n0 + it * 4 + j;
        const float* v = sv + j * 256;
        float a0 = sb[o], a1 = 0.f, a2 = 0.f, a3 = 0.f;
        #pragma unroll
        for (int f = 0; f < 128; f += 4) {
            a0 = fmaf(sWl[(f + 0) * 64 + o], v[f + 0], a0);
            a0 = fmaf(sWr[(f + 0) * 64 + o], v[128 + f + 0], a0);
            a1 = fmaf(sWl[(f + 1) * 64 + o], v[f + 1], a1);
            a1 = fmaf(sWr[(f + 1) * 64 + o], v[128 + f + 1], a1);
            a2 = fmaf(sWl[(f + 2) * 64 + o], v[f + 2], a2);
            a2 = fmaf(sWr[(f + 2) * 64 + o], v[128 + f + 2], a2);
            a3 = fmaf(sWl[(f + 3) * 64 + o], v[f + 3], a3);
            a3 = fmaf(sWr[(f + 3) * 64 + o], v[128 + f + 3], a3);
        }
        out[(size_t)n * FEAT + o] = (a0 + a1) + (a2 + a3);
        // double buffer: next iteration's loads go to the other half
    }
}

// ---------------------------------------------------------------------------
extern "C" void kernel_launch(void* const* d_in, const int* in_sizes, int n_in,
                              void* d_out, int out_size) {
    const float* x   = (const float*)d_in[0];
    const int*   ei  = (const int*)d_in[1];
    const float* W1l = (const float*)d_in[2];
    const float* b1l = (const float*)d_in[3];
    const float* W1r = (const float*)d_in[4];
    const float* W2l = (const float*)d_in[5];
    const float* b2l = (const float*)d_in[6];
    const float* W2r = (const float*)d_in[7];
    float* out = (float*)d_out;

    float *agg1, *agg2, *deg;
    cudaGetSymbolAddress((void**)&agg1, g_agg1);
    cudaGetSymbolAddress((void**)&agg2, g_agg2);
    cudaGetSymbolAddress((void**)&deg,  g_deg);

    const int SMEM1 = (8192 * 2 + 128 + 256) * 4;       // 67072 B
    const int SMEM2 = (8192 * 2 + 64 + 2048) * 4;       // 73984 B
    cudaFuncSetAttribute(layer1_kernel, cudaFuncAttributeMaxDynamicSharedMemorySize, SMEM1);
    cudaFuncSetAttribute(layer2_kernel, cudaFuncAttributeMaxDynamicSharedMemorySize, SMEM2);

    // Zero accumulators + degree
    zero_kernel<<<(N_NODES * FEAT / 4 + 255) / 256, 256>>>(agg1, N_NODES * FEAT / 4);
    zero_kernel<<<(N_NODES * HID / 4 + 255) / 256, 256>>>(agg2, N_NODES * HID / 4);
    zero_kernel<<<(N_NODES / 4 + 255) / 256, 256>>>(deg, N_NODES / 4);

    // Layer 1
    scatter1_kernel<<<(N_EDGES * 16 + 255) / 256, 256>>>(x, ei);
    layer1_kernel<<<N_NODES / L1_NPB, 128, SMEM1>>>(x, W1l, b1l, W1r);

    // Layer 2
    scatter2_kernel<<<(N_EDGES * 32 + 255) / 256, 256>>>(ei);
    layer2_kernel<<<N_NODES / 32, 256, SMEM2>>>(W2l, b2l, W2r, out);
}

// round 2
// speedup vs baseline: 2.0459x; 2.0459x over previous
#include <cuda_runtime.h>

#define N_NODES 100000
#define FEAT 64
#define HID 128
#define N_EDGES 1200000

// Scratch (device globals — no allocation allowed)
__device__ float g_agg1[N_NODES * FEAT];   // sum of x[src] at dst
__device__ float g_agg2[N_NODES * FEAT];   // sum of hl[src] at dst (64-dim thanks to linearity)
__device__ float g_h[N_NODES * HID];       // hidden activations
__device__ float g_hl[N_NODES * FEAT];     // h @ W2l.T (pre-aggregation)
__device__ float g_deg[N_NODES];           // in-degree (float)

// ---------------------------------------------------------------------------
__device__ __forceinline__ void red4(float* p, float4 v) {
    asm volatile("red.global.add.v4.f32 [%0], {%1,%2,%3,%4};"
                 :: "l"(p), "f"(v.x), "f"(v.y), "f"(v.z), "f"(v.w) : "memory");
}

__global__ void zero_kernel(float* p, int n4) {
    int i = blockIdx.x * blockDim.x + threadIdx.x;
    if (i < n4) ((float4*)p)[i] = make_float4(0.f, 0.f, 0.f, 0.f);
}

// ---------------------------------------------------------------------------
// Scatter: 4 threads per edge, each handles 16 floats (4 x red.v4) of a 64-dim row.
__global__ void scatter_kernel(const float* __restrict__ vals,
                               const int* __restrict__ ei,
                               float* __restrict__ agg,
                               int do_deg) {
    int idx = blockIdx.x * blockDim.x + threadIdx.x;
    if (idx >= N_EDGES * 4) return;
    int e = idx >> 2;
    int c = idx & 3;
    int src = ei[e];
    int dst = ei[N_EDGES + e];
    const float4* vs = (const float4*)(vals + (size_t)src * FEAT) + c * 4;
    float* base = agg + (size_t)dst * FEAT + c * 16;
    float4 v0 = vs[0], v1 = vs[1], v2 = vs[2], v3 = vs[3];
    red4(base + 0,  v0);
    red4(base + 4,  v1);
    red4(base + 8,  v2);
    red4(base + 12, v3);
    if (do_deg && c == 0) atomicAdd(&g_deg[dst], 1.0f);
}

// ---------------------------------------------------------------------------
// Layer 1: h[n,t] = relu( W1l[t,:].(agg1[n]/deg) + b1l[t] + W1r[t,:].x[n] )
// block = 128 threads (t = hidden channel), 8-node register tile, 10 tiles/block.
#define L1_TILES 10
__global__ void layer1_kernel(const float* __restrict__ x,
                              const float* __restrict__ W1l,
                              const float* __restrict__ b1l,
                              const float* __restrict__ W1r) {
    extern __shared__ float sm[];
    float* sW = sm;                  // 16384: [f*128 + t], f<64 -> W1l, f>=64 -> W1r
    float* sb = sm + 16384;          // 128
    float* sv = sm + 16512;          // 8 * 128: per node [agg(64, pre-scaled) | x(64)]

    int t = threadIdx.x;
    #pragma unroll 1
    for (int s = 0; s < 128; s++) {
        sW[s * 128 + t] = (s < 64) ? W1l[t * 64 + s] : W1r[t * 64 + (s - 64)];
    }
    sb[t] = b1l[t];
    __syncthreads();

    int nbase = blockIdx.x * (L1_TILES * 8);
    for (int tile = 0; tile < L1_TILES; tile++) {
        int n0 = nbase + tile * 8;
        // load 8-node vector tile
        #pragma unroll
        for (int s = 0; s < 8; s++) {
            int k = t + s * 128;
            int j = k >> 7;
            int f = k & 127;
            int n = n0 + j;
            float val;
            if (f < 64) val = g_agg1[(size_t)n * FEAT + f] / fmaxf(g_deg[n], 1.0f);
            else        val = x[(size_t)n * FEAT + (f - 64)];
            sv[k] = val;
        }
        __syncthreads();

        float acc[8];
        #pragma unroll
        for (int j = 0; j < 8; j++) acc[j] = sb[t];

        #pragma unroll 4
        for (int f = 0; f < 128; f += 4) {
            float w0 = sW[(f + 0) * 128 + t];
            float w1 = sW[(f + 1) * 128 + t];
            float w2 = sW[(f + 2) * 128 + t];
            float w3 = sW[(f + 3) * 128 + t];
            #pragma unroll
            for (int j = 0; j < 8; j++) {
                float4 v = *(const float4*)&sv[j * 128 + f];
                acc[j] = fmaf(w0, v.x, acc[j]);
                acc[j] = fmaf(w1, v.y, acc[j]);
                acc[j] = fmaf(w2, v.z, acc[j]);
                acc[j] = fmaf(w3, v.w, acc[j]);
            }
        }
        #pragma unroll
        for (int j = 0; j < 8; j++)
            g_h[(size_t)(n0 + j) * HID + t] = fmaxf(acc[j], 0.0f);
        __syncthreads();
    }
}

// ---------------------------------------------------------------------------
// GEMM2: hl[n,o] = W2l[o,:].h[n]  (o = t<64),  hr[n,o] = W2r[o,:].h[n] (t>=64)
// hr goes straight into out; hl goes to g_hl for scattering.
#define L2_TILES 10
__global__ void gemm2_kernel(const float* __restrict__ W2l,
                             const float* __restrict__ W2r,
                             float* __restrict__ out) {
    extern __shared__ float sm[];
    float* sW = sm;                  // 16384: [f*128 + t], t<64 -> W2l[t][f], t>=64 -> W2r[t-64][f]
    float* sv = sm + 16384;          // 8 * 128: h rows

    int t = threadIdx.x;
    #pragma unroll 1
    for (int s = 0; s < 128; s++) {
        sW[s * 128 + t] = (t < 64) ? W2l[t * 128 + s] : W2r[(t - 64) * 128 + s];
    }
    __syncthreads();

    int nbase = blockIdx.x * (L2_TILES * 8);
    for (int tile = 0; tile < L2_TILES; tile++) {
        int n0 = nbase + tile * 8;
        #pragma unroll
        for (int s = 0; s < 8; s++) {
            int k = t + s * 128;
            int j = k >> 7;
            int f = k & 127;
            sv[k] = g_h[(size_t)(n0 + j) * HID + f];
        }
        __syncthreads();

        float acc[8];
        #pragma unroll
        for (int j = 0; j < 8; j++) acc[j] = 0.0f;

        #pragma unroll 4
        for (int f = 0; f < 128; f += 4) {
            float w0 = sW[(f + 0) * 128 + t];
            float w1 = sW[(f + 1) * 128 + t];
            float w2 = sW[(f + 2) * 128 + t];
            float w3 = sW[(f + 3) * 128 + t];
            #pragma unroll
            for (int j = 0; j < 8; j++) {
                float4 v = *(const float4*)&sv[j * 128 + f];
                acc[j] = fmaf(w0, v.x, acc[j]);
                acc[j] = fmaf(w1, v.y, acc[j]);
                acc[j] = fmaf(w2, v.z, acc[j]);
                acc[j] = fmaf(w3, v.w, acc[j]);
            }
        }
        #pragma unroll
        for (int j = 0; j < 8; j++) {
            int n = n0 + j;
            if (t < 64) g_hl[(size_t)n * FEAT + t] = acc[j];
            else        out[(size_t)n * FEAT + (t - 64)] = acc[j];
        }
        __syncthreads();
    }
}

// ---------------------------------------------------------------------------
// Final: out[n,o] += agg2[n,o]/deg[n] + b2l[o]   (float4-vectorized)
__global__ void final_kernel(float* __restrict__ out,
                             const float* __restrict__ b2l) {
    int i4 = blockIdx.x * blockDim.x + threadIdx.x;
    if (i4 >= N_NODES * FEAT / 4) return;
    int n = i4 >> 4;
    int o4 = i4 & 15;
    float inv = 1.0f / fmaxf(g_deg[n], 1.0f);
    float4 a = ((const float4*)g_agg2)[i4];
    float4 b = ((const float4*)b2l)[o4];
    float4 y = ((float4*)out)[i4];
    y.x += a.x * inv + b.x;
    y.y += a.y * inv + b.y;
    y.z += a.z * inv + b.z;
    y.w += a.w * inv + b.w;
    ((float4*)out)[i4] = y;
}

// ---------------------------------------------------------------------------
extern "C" void kernel_launch(void* const* d_in, const int* in_sizes, int n_in,
                              void* d_out, int out_size) {
    const float* x   = (const float*)d_in[0];
    const int*   ei  = (const int*)d_in[1];
    const float* W1l = (const float*)d_in[2];
    const float* b1l = (const float*)d_in[3];
    const float* W1r = (const float*)d_in[4];
    const float* W2l = (const float*)d_in[5];
    const float* b2l = (const float*)d_in[6];
    const float* W2r = (const float*)d_in[7];
    float* out = (float*)d_out;

    float *agg1, *agg2, *deg, *hl;
    cudaGetSymbolAddress((void**)&agg1, g_agg1);
    cudaGetSymbolAddress((void**)&agg2, g_agg2);
    cudaGetSymbolAddress((void**)&deg,  g_deg);
    cudaGetSymbolAddress((void**)&hl,   g_hl);

    const int SMEM1 = (16384 + 128 + 1024) * 4;   // 70144 B
    const int SMEM2 = (16384 + 1024) * 4;         // 69632 B
    cudaFuncSetAttribute(layer1_kernel, cudaFuncAttributeMaxDynamicSharedMemorySize, SMEM1);
    cudaFuncSetAttribute(gemm2_kernel,  cudaFuncAttributeMaxDynamicSharedMemorySize, SMEM2);

    // Zero accumulators + degree
    zero_kernel<<<(N_NODES * FEAT / 4 + 255) / 256, 256>>>(agg1, N_NODES * FEAT / 4);
    zero_kernel<<<(N_NODES * FEAT / 4 + 255) / 256, 256>>>(agg2, N_NODES * FEAT / 4);
    zero_kernel<<<(N_NODES / 4 + 255) / 256, 256>>>(deg, N_NODES / 4);

    // Layer 1: scatter x, then fused (lin_l + lin_r + relu)
    scatter_kernel<<<(N_EDGES * 4 + 255) / 256, 256>>>(x, ei, agg1, 1);
    layer1_kernel<<<N_NODES / (L1_TILES * 8), 128, SMEM1>>>(x, W1l, b1l, W1r);

    // Layer 2: GEMM first (linearity), scatter 64-dim hl, then cheap epilogue
    gemm2_kernel<<<N_NODES / (L2_TILES * 8), 128, SMEM2>>>(W2l, W2r, out);
    scatter_kernel<<<(N_EDGES * 4 + 255) / 256, 256>>>(hl, ei, agg2, 0);
    final_kernel<<<(N_NODES * FEAT / 4 + 255) / 256, 256>>>(out, b2l);
}

// round 3
// speedup vs baseline: 2.3470x; 1.1471x over previous
#include <cuda_runtime.h>

#define N_NODES 100000
#define FEAT 64
#define HID 128
#define N_EDGES 1200000
#define NP 129          // padded stride for f-major node tile (conflict-free)

// Scratch (device globals — no allocation allowed)
__device__ float g_agg1[N_NODES * FEAT];   // sum of x[src] at dst
__device__ float g_agg2[N_NODES * FEAT];   // sum of hl[src] at dst
__device__ float g_h[N_NODES * HID];       // hidden activations
__device__ float g_hl[N_NODES * FEAT];     // h @ W2l.T (pre-aggregation)
__device__ float g_deg[N_NODES];           // in-degree
__device__ float g_invdeg[N_NODES];        // 1/max(deg,1)

// ---------------------------------------------------------------------------
__device__ __forceinline__ void red4(float* p, float4 v) {
    asm volatile("red.global.add.v4.f32 [%0], {%1,%2,%3,%4};"
                 :: "l"(p), "f"(v.x), "f"(v.y), "f"(v.z), "f"(v.w) : "memory");
}

__global__ void zero_kernel(float* p, int n4) {
    int i = blockIdx.x * blockDim.x + threadIdx.x;
    if (i < n4) ((float4*)p)[i] = make_float4(0.f, 0.f, 0.f, 0.f);
}

__global__ void invdeg_kernel() {
    int n = blockIdx.x * blockDim.x + threadIdx.x;
    if (n < N_NODES) g_invdeg[n] = 1.0f / fmaxf(g_deg[n], 1.0f);
}

// ---------------------------------------------------------------------------
// Scatter: 4 threads per edge, each handles 16 floats (4 x red.v4) of a 64-dim row.
__global__ void scatter_kernel(const float* __restrict__ vals,
                               const int* __restrict__ ei,
                               float* __restrict__ agg,
                               int do_deg) {
    int idx = blockIdx.x * blockDim.x + threadIdx.x;
    if (idx >= N_EDGES * 4) return;
    int e = idx >> 2;
    int c = idx & 3;
    int src = ei[e];
    int dst = ei[N_EDGES + e];
    const float4* vs = (const float4*)(vals + (size_t)src * FEAT) + c * 4;
    float* base = agg + (size_t)dst * FEAT + c * 16;
    float4 v0 = vs[0], v1 = vs[1], v2 = vs[2], v3 = vs[3];
    red4(base + 0,  v0);
    red4(base + 4,  v1);
    red4(base + 8,  v2);
    red4(base + 12, v3);
    if (do_deg && c == 0) atomicAdd(&g_deg[dst], 1.0f);
}

// ---------------------------------------------------------------------------
// Layer 1 GEMM: h[n,ch] = relu( Wcat[ch,:].v[n] + b[ch] ),
// v[n] = [agg1[n]*invdeg[n] (64) | x[n] (64)], Wcat = [W1l | W1r] (128x128).
// Block 256 thr: tx = t&15 (8-ch group), ty = t>>4 (8-node group). Tile 128ch x 128n.
__global__ void __launch_bounds__(256, 1)
layer1_kernel(const float* __restrict__ x,
              const float* __restrict__ W1l,
              const float* __restrict__ b1l,
              const float* __restrict__ W1r) {
    extern __shared__ float sm[];
    float* sW = sm;                    // 16384: [f*128 + ch]
    float* sv = sm + 16384;            // 128 * NP: [j*NP + f]
    float* sb = sm + 16384 + 128 * NP; // 128

    int t = threadIdx.x;
    int tx = t & 15, ty = t >> 4;
    int n0 = blockIdx.x * 128;

    // weights: f<64 -> W1l[ch][f], f>=64 -> W1r[ch][f-64]
    for (int i = t; i < 128 * 128; i += 256) {
        int ch = i >> 7, f = i & 127;
        float w = (f < 64) ? W1l[ch * 64 + f] : W1r[ch * 64 + (f - 64)];
        sW[f * 128 + ch] = w;
    }
    if (t < 128) sb[t] = b1l[t];

    // node tile, f-major: coalesced global reads, conflict-free STS
    for (int i = t; i < 128 * 128; i += 256) {
        int j = i >> 7, f = i & 127;
        int n = n0 + j;
        float val = 0.0f;
        if (n < N_NODES) {
            if (f < 64) val = g_agg1[(size_t)n * FEAT + f] * g_invdeg[n];
            else        val = x[(size_t)n * FEAT + (f - 64)];
        }
        sv[j * NP + f] = val;
    }
    __syncthreads();

    int ch0 = tx * 8, j0 = ty * 8;
    float acc[8][8];
    #pragma unroll
    for (int c = 0; c < 8; c++) {
        float b = sb[ch0 + c];
        #pragma unroll
        for (int j = 0; j < 8; j++) acc[c][j] = (j == 0) ? b : 0.0f;
    }

    #pragma unroll 8
    for (int k = 0; k < 128; k++) {
        float4 wa = *(const float4*)&sW[k * 128 + ch0];
        float4 wb = *(const float4*)&sW[k * 128 + ch0 + 4];
        float vv[8];
        #pragma unroll
        for (int j = 0; j < 8; j++) vv[j] = sv[(j0 + j) * NP + k];
        #pragma unroll
        for (int j = 0; j < 8; j++) {
            acc[0][j] = fmaf(wa.x, vv[j], acc[0][j]);
            acc[1][j] = fmaf(wa.y, vv[j], acc[1][j]);
            acc[2][j] = fmaf(wa.z, vv[j], acc[2][j]);
            acc[3][j] = fmaf(wa.w, vv[j], acc[3][j]);
            acc[4][j] = fmaf(wb.x, vv[j], acc[4][j]);
            acc[5][j] = fmaf(wb.y, vv[j], acc[5][j]);
            acc[6][j] = fmaf(wb.z, vv[j], acc[6][j]);
            acc[7][j] = fmaf(wb.w, vv[j], acc[7][j]);
        }
    }

    // combine bias (was folded into j==0 only — fix: add bias to all j)
    #pragma unroll
    for (int j = 0; j < 8; j++) {
        int n = n0 + j0 + j;
        if (n >= N_NODES) continue;
        float4 o0, o1;
        float b;
        // bias: acc[c][0] already has it; for j>0 add sb
        o0.x = fmaxf(acc[0][j] + ((j == 0) ? 0.f : sb[ch0 + 0]), 0.f);
        o0.y = fmaxf(acc[1][j] + ((j == 0) ? 0.f : sb[ch0 + 1]), 0.f);
        o0.z = fmaxf(acc[2][j] + ((j == 0) ? 0.f : sb[ch0 + 2]), 0.f);
        o0.w = fmaxf(acc[3][j] + ((j == 0) ? 0.f : sb[ch0 + 3]), 0.f);
        o1.x = fmaxf(acc[4][j] + ((j == 0) ? 0.f : sb[ch0 + 4]), 0.f);
        o1.y = fmaxf(acc[5][j] + ((j == 0) ? 0.f : sb[ch0 + 5]), 0.f);
        o1.z = fmaxf(acc[6][j] + ((j == 0) ? 0.f : sb[ch0 + 6]), 0.f);
        o1.w = fmaxf(acc[7][j] + ((j == 0) ? 0.f : sb[ch0 + 7]), 0.f);
        float* hp = g_h + (size_t)n * HID + ch0;
        *(float4*)(hp + 0) = o0;
        *(float4*)(hp + 4) = o1;
    }
}

// ---------------------------------------------------------------------------
// GEMM2: ch<64 -> g_hl[n][ch] = W2l[ch,:].h[n];  ch>=64 -> out[n][ch-64] = W2r[ch-64,:].h[n]
__global__ void __launch_bounds__(256, 1)
gemm2_kernel(const float* __restrict__ W2l,
             const float* __restrict__ W2r,
             float* __restrict__ out) {
    extern __shared__ float sm[];
    float* sW = sm;                 // 16384: [f*128 + ch]
    float* sv = sm + 16384;         // 128 * NP

    int t = threadIdx.x;
    int tx = t & 15, ty = t >> 4;
    int n0 = blockIdx.x * 128;

    for (int i = t; i < 128 * 128; i += 256) {
        int ch = i >> 7, f = i & 127;
        float w = (ch < 64) ? W2l[ch * 128 + f] : W2r[(ch - 64) * 128 + f];
        sW[f * 128 + ch] = w;
    }
    for (int i = t; i < 128 * 128; i += 256) {
        int j = i >> 7, f = i & 127;
        int n = n0 + j;
        sv[j * NP + f] = (n < N_NODES) ? g_h[(size_t)n * HID + f] : 0.0f;
    }
    __syncthreads();

    int ch0 = tx * 8, j0 = ty * 8;
    float acc[8][8];
    #pragma unroll
    for (int c = 0; c < 8; c++)
        #pragma unroll
        for (int j = 0; j < 8; j++) acc[c][j] = 0.0f;

    #pragma unroll 8
    for (int k = 0; k < 128; k++) {
        float4 wa = *(const float4*)&sW[k * 128 + ch0];
        float4 wb = *(const float4*)&sW[k * 128 + ch0 + 4];
        float vv[8];
        #pragma unroll
        for (int j = 0; j < 8; j++) vv[j] = sv[(j0 + j) * NP + k];
        #pragma unroll
        for (int j = 0; j < 8; j++) {
            acc[0][j] = fmaf(wa.x, vv[j], acc[0][j]);
            acc[1][j] = fmaf(wa.y, vv[j], acc[1][j]);
            acc[2][j] = fmaf(wa.z, vv[j], acc[2][j]);
            acc[3][j] = fmaf(wa.w, vv[j], acc[3][j]);
            acc[4][j] = fmaf(wb.x, vv[j], acc[4][j]);
            acc[5][j] = fmaf(wb.y, vv[j], acc[5][j]);
            acc[6][j] = fmaf(wb.z, vv[j], acc[6][j]);
            acc[7][j] = fmaf(wb.w, vv[j], acc[7][j]);
        }
    }

    #pragma unroll
    for (int j = 0; j < 8; j++) {
        int n = n0 + j0 + j;
        if (n >= N_NODES) continue;
        float4 o0 = make_float4(acc[0][j], acc[1][j], acc[2][j], acc[3][j]);
        float4 o1 = make_float4(acc[4][j], acc[5][j], acc[6][j], acc[7][j]);
        if (tx < 8) {   // ch0 in [0,64): both halves go to g_hl
            float* p = g_hl + (size_t)n * FEAT + ch0;
            *(float4*)(p + 0) = o0;
            *(float4*)(p + 4) = o1;
        } else {        // ch0 in [64,128): out
            float* p = out + (size_t)n * FEAT + (ch0 - 64);
            *(float4*)(p + 0) = o0;
            *(float4*)(p + 4) = o1;
        }
    }
}

// ---------------------------------------------------------------------------
// Final: out[n,o] += agg2[n,o]*invdeg[n] + b2l[o]
__global__ void final_kernel(float* __restrict__ out,
                             const float* __restrict__ b2l) {
    int i4 = blockIdx.x * blockDim.x + threadIdx.x;
    if (i4 >= N_NODES * FEAT / 4) return;
    int n = i4 >> 4;
    int o4 = i4 & 15;
    float inv = g_invdeg[n];
    float4 a = ((const float4*)g_agg2)[i4];
    float4 b = ((const float4*)b2l)[o4];
    float4 y = ((float4*)out)[i4];
    y.x += a.x * inv + b.x;
    y.y += a.y * inv + b.y;
    y.z += a.z * inv + b.z;
    y.w += a.w * inv + b.w;
    ((float4*)out)[i4] = y;
}

// ---------------------------------------------------------------------------
extern "C" void kernel_launch(void* const* d_in, const int* in_sizes, int n_in,
                              void* d_out, int out_size) {
    const float* x   = (const float*)d_in[0];
    const int*   ei  = (const int*)d_in[1];
    const float* W1l = (const float*)d_in[2];
    const float* b1l = (const float*)d_in[3];
    const float* W1r = (const float*)d_in[4];
    const float* W2l = (const float*)d_in[5];
    const float* b2l = (const float*)d_in[6];
    const float* W2r = (const float*)d_in[7];
    float* out = (float*)d_out;

    float *agg1, *agg2, *deg, *hl;
    cudaGetSymbolAddress((void**)&agg1, g_agg1);
    cudaGetSymbolAddress((void**)&agg2, g_agg2);
    cudaGetSymbolAddress((void**)&deg,  g_deg);
    cudaGetSymbolAddress((void**)&hl,   g_hl);

    const int SMEM1 = (16384 + 128 * NP + 128) * 4;
    const int SMEM2 = (16384 + 128 * NP) * 4;
    cudaFuncSetAttribute(layer1_kernel, cudaFuncAttributeMaxDynamicSharedMemorySize, SMEM1);
    cudaFuncSetAttribute(gemm2_kernel,  cudaFuncAttributeMaxDynamicSharedMemorySize, SMEM2);

    const int NT = (N_NODES + 127) / 128;   // 782

    // Zero accumulators + degree
    zero_kernel<<<(N_NODES * FEAT / 4 + 255) / 256, 256>>>(agg1, N_NODES * FEAT / 4);
    zero_kernel<<<(N_NODES * FEAT / 4 + 255) / 256, 256>>>(agg2, N_NODES * FEAT / 4);
    zero_kernel<<<(N_NODES / 4 + 255) / 256, 256>>>(deg, N_NODES / 4);

    // Layer 1
    scatter_kernel<<<(N_EDGES * 4 + 255) / 256, 256>>>(x, ei, agg1, 1);
    invdeg_kernel<<<(N_NODES + 255) / 256, 256>>>();
    layer1_kernel<<<NT, 256, SMEM1>>>(x, W1l, b1l, W1r);

    // Layer 2: GEMM first (linearity), scatter 64-dim hl, then epilogue
    gemm2_kernel<<<NT, 256, SMEM2>>>(W2l, W2r, out);
    scatter_kernel<<<(N_EDGES * 4 + 255) / 256, 256>>>(hl, ei, agg2, 0);
    final_kernel<<<(N_NODES * FEAT / 4 + 255) / 256, 256>>>(out, b2l);
}

// round 4
// speedup vs baseline: 3.5314x; 1.5047x over previous
#include <cuda_runtime.h>

#define N_NODES 100000
#define FEAT 64
#define HID 128
#define N_EDGES 1200000
#define NP 132              // padded f-stride (multiple of 4 for STS.128, 4 mod 32 banks)
#define SCAN_B 1024         // elements per scan block
#define N_SCANB 98          // ceil(100000/1024)

// Scratch (device globals — no allocation allowed)
__device__ float g_agg[N_NODES * FEAT];    // mean-aggregated features (reused both layers)
__device__ float g_h[N_NODES * HID];       // hidden activations
__device__ float g_hl[N_NODES * FEAT];     // h @ W2l.T (pre-aggregation)
__device__ float g_invdeg[N_NODES];
__device__ int   g_cnt[N_NODES];
__device__ int   g_rowptr[N_NODES];
__device__ int   g_cursor[N_NODES];
__device__ int   g_csr[N_EDGES];           // src indices grouped by dst
__device__ int   g_bsum[N_SCANB];
__device__ int   g_boff[N_SCANB];

// ---------------------------------------------------------------------------
__global__ void zero_kernel(float* p, int n4) {
    int i = blockIdx.x * blockDim.x + threadIdx.x;
    if (i < n4) ((float4*)p)[i] = make_float4(0.f, 0.f, 0.f, 0.f);
}

// ---------------------------------------------------------------------------
// CSR build
__global__ void hist_kernel(const int* __restrict__ ei) {
    int e = blockIdx.x * blockDim.x + threadIdx.x;
    if (e < N_EDGES) atomicAdd(&g_cnt[ei[N_EDGES + e]], 1);
}

__global__ void scan1_kernel() {            // grid N_SCANB, block 256; 4 elems/thread
    __shared__ int ws[8];
    int b = blockIdx.x, t = threadIdx.x;
    int base = b * SCAN_B + t * 4;
    int c0 = (base + 0 < N_NODES) ? g_cnt[base + 0] : 0;
    int c1 = (base + 1 < N_NODES) ? g_cnt[base + 1] : 0;
    int c2 = (base + 2 < N_NODES) ? g_cnt[base + 2] : 0;
    int c3 = (base + 3 < N_NODES) ? g_cnt[base + 3] : 0;
    int s = c0 + c1 + c2 + c3;
    int lane = t & 31, w = t >> 5;
    int v = s;
    #pragma unroll
    for (int d = 1; d < 32; d <<= 1) {
        int u = __shfl_up_sync(~0u, v, d);
        if (lane >= d) v += u;
    }
    if (lane == 31) ws[w] = v;
    __syncthreads();
    if (t < 8) {
        int u = ws[t];
        #pragma unroll
        for (int d = 1; d < 8; d <<= 1) {
            int uu = __shfl_up_sync(0xffu, u, d);
            if (t >= d) u += uu;
        }
        ws[t] = u;
    }
    __syncthreads();
    int prefix = v - s + ((w > 0) ? ws[w - 1] : 0);   // exclusive prefix of this thread
    int r0 = prefix, r1 = r0 + c0, r2 = r1 + c1, r3 = r2 + c2;
    if (base + 0 < N_NODES) g_rowptr[base + 0] = r0;
    if (base + 1 < N_NODES) g_rowptr[base + 1] = r1;
    if (base + 2 < N_NODES) g_rowptr[base + 2] = r2;
    if (base + 3 < N_NODES) g_rowptr[base + 3] = r3;
    if (t == 255) g_bsum[b] = ws[7];
}

__global__ void scan2_kernel() {            // 1 block, 128 threads
    __shared__ int s[128];
    int t = threadIdx.x;
    int v = (t < N_SCANB) ? g_bsum[t] : 0;
    s[t] = v;
    __syncthreads();
    #pragma unroll
    for (int d = 1; d < 128; d <<= 1) {
        int u = (t >= d) ? s[t - d] : 0;
        __syncthreads();
        s[t] += u;
        __syncthreads();
    }
    if (t < N_SCANB) g_boff[t] = s[t] - v;  // exclusive
}

__global__ void scan3_kernel() {
    int i = blockIdx.x * blockDim.x + threadIdx.x;
    if (i >= N_NODES) return;
    int r = g_rowptr[i] + g_boff[i / SCAN_B];
    g_rowptr[i] = r;
    g_cursor[i] = r;
    g_invdeg[i] = 1.0f / fmaxf((float)g_cnt[i], 1.0f);
}

__global__ void fill_kernel(const int* __restrict__ ei) {
    int e = blockIdx.x * blockDim.x + threadIdx.x;
    if (e >= N_EDGES) return;
    int src = ei[e];
    int dst = ei[N_EDGES + e];
    int pos = atomicAdd(&g_cursor[dst], 1);
    g_csr[pos] = src;
}

// ---------------------------------------------------------------------------
// Gather (mean aggregation): one warp per node, 64-dim rows, float2 per lane.
__global__ void gather_kernel(const float* __restrict__ vals,
                              float* __restrict__ aggm) {
    int gw = (blockIdx.x * blockDim.x + threadIdx.x) >> 5;
    if (gw >= N_NODES) return;
    int lane = threadIdx.x & 31;
    int start = g_rowptr[gw];
    int deg = g_cnt[gw];
    const float2* v2 = (const float2*)vals;
    float2 a0 = make_float2(0.f, 0.f), a1 = make_float2(0.f, 0.f);
    int i = 0;
    for (; i + 2 <= deg; i += 2) {
        int s0 = g_csr[start + i];
        int s1 = g_csr[start + i + 1];
        float2 u0 = v2[(size_t)s0 * 32 + lane];
        float2 u1 = v2[(size_t)s1 * 32 + lane];
        a0.x += u0.x; a0.y += u0.y;
        a1.x += u1.x; a1.y += u1.y;
    }
    if (i < deg) {
        int s0 = g_csr[start + i];
        float2 u0 = v2[(size_t)s0 * 32 + lane];
        a0.x += u0.x; a0.y += u0.y;
    }
    float inv = g_invdeg[gw];
    float2 r = make_float2((a0.x + a1.x) * inv, (a0.y + a1.y) * inv);
    ((float2*)aggm)[(size_t)gw * 32 + lane] = r;
}

// ---------------------------------------------------------------------------
// Layer 1 GEMM: h[n,ch] = relu( Wcat[ch,:].v[n] + b[ch] ),
// v[n] = [aggm[n] (64) | x[n] (64)]. Tile: 128 ch x 64 nodes, 2 CTAs/SM.
__global__ void __launch_bounds__(256, 2)
layer1_kernel(const float* __restrict__ x,
              const float* __restrict__ W1l,
              const float* __restrict__ b1l,
              const float* __restrict__ W1r) {
    extern __shared__ float sm[];
    float* sW = sm;                    // 16384: [f*128 + ch]
    float* sv = sm + 16384;            // 64 * NP: [j*NP + f]
    float* sb = sm + 16384 + 64 * NP;  // 128

    int t = threadIdx.x;
    int tx = t & 15, ty = t >> 4;
    int n0 = blockIdx.x * 64;

    // weights: 4096 float4, ch-fast mapping (conflict-free STS)
    for (int i = t; i < 4096; i += 256) {
        int ch = i & 127, fq = i >> 7;    // fq in [0,32)
        float4 w = (fq < 16) ? ((const float4*)W1l)[ch * 16 + fq]
                             : ((const float4*)W1r)[ch * 16 + (fq - 16)];
        int f = fq * 4;
        sW[(f + 0) * 128 + ch] = w.x;
        sW[(f + 1) * 128 + ch] = w.y;
        sW[(f + 2) * 128 + ch] = w.z;
        sW[(f + 3) * 128 + ch] = w.w;
    }
    if (t < 128) sb[t] = b1l[t];

    // node tile: 2048 float4 (64 nodes x 128 f), warp = one node row
    for (int i = t; i < 2048; i += 256) {
        int j = i >> 5, f4 = i & 31;
        int n = n0 + j;
        float4 v = make_float4(0.f, 0.f, 0.f, 0.f);
        if (n < N_NODES) {
            v = (f4 < 16) ? ((const float4*)g_agg)[(size_t)n * 16 + f4]
                          : ((const float4*)x)[(size_t)n * 16 + (f4 - 16)];
        }
        *(float4*)&sv[j * NP + f4 * 4] = v;
    }
    __syncthreads();

    int ch0 = tx * 8, j0 = ty * 4;
    float acc[8][4];
    #pragma unroll
    for (int c = 0; c < 8; c++) {
        float b = sb[ch0 + c];
        #pragma unroll
        for (int j = 0; j < 4; j++) acc[c][j] = b;
    }

    #pragma unroll 8
    for (int k = 0; k < 128; k++) {
        float4 wa = *(const float4*)&sW[k * 128 + ch0];
        float4 wb = *(const float4*)&sW[k * 128 + ch0 + 4];
        float vv[4];
        #pragma unroll
        for (int j = 0; j < 4; j++) vv[j] = sv[(j0 + j) * NP + k];
        #pragma unroll
        for (int j = 0; j < 4; j++) {
            acc[0][j] = fmaf(wa.x, vv[j], acc[0][j]);
            acc[1][j] = fmaf(wa.y, vv[j], acc[1][j]);
            acc[2][j] = fmaf(wa.z, vv[j], acc[2][j]);
            acc[3][j] = fmaf(wa.w, vv[j], acc[3][j]);
            acc[4][j] = fmaf(wb.x, vv[j], acc[4][j]);
            acc[5][j] = fmaf(wb.y, vv[j], acc[5][j]);
            acc[6][j] = fmaf(wb.z, vv[j], acc[6][j]);
            acc[7][j] = fmaf(wb.w, vv[j], acc[7][j]);
        }
    }

    #pragma unroll
    for (int j = 0; j < 4; j++) {
        int n = n0 + j0 + j;
        if (n >= N_NODES) continue;
        float4 o0 = make_float4(fmaxf(acc[0][j], 0.f), fmaxf(acc[1][j], 0.f),
                                fmaxf(acc[2][j], 0.f), fmaxf(acc[3][j], 0.f));
        float4 o1 = make_float4(fmaxf(acc[4][j], 0.f), fmaxf(acc[5][j], 0.f),
                                fmaxf(acc[6][j], 0.f), fmaxf(acc[7][j], 0.f));
        float* hp = g_h + (size_t)n * HID + ch0;
        *(float4*)(hp + 0) = o0;
        *(float4*)(hp + 4) = o1;
    }
}

// ---------------------------------------------------------------------------
// GEMM2: ch<64 -> g_hl[n][ch] = W2l[ch,:].h[n];  ch>=64 -> out[n][ch-64] = W2r.
__global__ void __launch_bounds__(256, 2)
gemm2_kernel(const float* __restrict__ W2l,
             const float* __restrict__ W2r,
             float* __restrict__ out) {
    extern __shared__ float sm[];
    float* sW = sm;                 // 16384: [f*128 + ch]
    float* sv = sm + 16384;         // 64 * NP

    int t = threadIdx.x;
    int tx = t & 15, ty = t >> 4;
    int n0 = blockIdx.x * 64;

    for (int i = t; i < 4096; i += 256) {
        int ch = i & 127, fq = i >> 7;
        float4 w = (ch < 64) ? ((const float4*)W2l)[ch * 32 + fq]
                             : ((const float4*)W2r)[(ch - 64) * 32 + fq];
        int f = fq * 4;
        sW[(f + 0) * 128 + ch] = w.x;
        sW[(f + 1) * 128 + ch] = w.y;
        sW[(f + 2) * 128 + ch] = w.z;
        sW[(f + 3) * 128 + ch] = w.w;
    }
    for (int i = t; i < 2048; i += 256) {
        int j = i >> 5, f4 = i & 31;
        int n = n0 + j;
        float4 v = make_float4(0.f, 0.f, 0.f, 0.f);
        if (n < N_NODES) v = ((const float4*)g_h)[(size_t)n * 32 + f4];
        *(float4*)&sv[j * NP + f4 * 4] = v;
    }
    __syncthreads();

    int ch0 = tx * 8, j0 = ty * 4;
    float acc[8][4];
    #pragma unroll
    for (int c = 0; c < 8; c++)
        #pragma unroll
        for (int j = 0; j < 4; j++) acc[c][j] = 0.0f;

    #pragma unroll 8
    for (int k = 0; k < 128; k++) {
        float4 wa = *(const float4*)&sW[k * 128 + ch0];
        float4 wb = *(const float4*)&sW[k * 128 + ch0 + 4];
        float vv[4];
        #pragma unroll
        for (int j = 0; j < 4; j++) vv[j] = sv[(j0 + j) * NP + k];
        #pragma unroll
        for (int j = 0; j < 4; j++) {
            acc[0][j] = fmaf(wa.x, vv[j], acc[0][j]);
            acc[1][j] = fmaf(wa.y, vv[j], acc[1][j]);
            acc[2][j] = fmaf(wa.z, vv[j], acc[2][j]);
            acc[3][j] = fmaf(wa.w, vv[j], acc[3][j]);
            acc[4][j] = fmaf(wb.x, vv[j], acc[4][j]);
            acc[5][j] = fmaf(wb.y, vv[j], acc[5][j]);
            acc[6][j] = fmaf(wb.z, vv[j], acc[6][j]);
            acc[7][j] = fmaf(wb.w, vv[j], acc[7][j]);
        }
    }

    #pragma unroll
    for (int j = 0; j < 4; j++) {
        int n = n0 + j0 + j;
        if (n >= N_NODES) continue;
        float4 o0 = make_float4(acc[0][j], acc[1][j], acc[2][j], acc[3][j]);
        float4 o1 = make_float4(acc[4][j], acc[5][j], acc[6][j], acc[7][j]);
        if (tx < 8) {
            float* p = g_hl + (size_t)n * FEAT + ch0;
            *(float4*)(p + 0) = o0;
            *(float4*)(p + 4) = o1;
        } else {
            float* p = out + (size_t)n * FEAT + (ch0 - 64);
            *(float4*)(p + 0) = o0;
            *(float4*)(p + 4) = o1;
        }
    }
}

// ---------------------------------------------------------------------------
// Final: out[n,o] += aggm2[n,o] + b2l[o]   (mean already applied in gather)
__global__ void final_kernel(float* __restrict__ out,
                             const float* __restrict__ b2l) {
    int i4 = blockIdx.x * blockDim.x + threadIdx.x;
    if (i4 >= N_NODES * FEAT / 4) return;
    int o4 = i4 & 15;
    float4 a = ((const float4*)g_agg)[i4];
    float4 b = ((const float4*)b2l)[o4];
    float4 y = ((float4*)out)[i4];
    y.x += a.x + b.x;
    y.y += a.y + b.y;
    y.z += a.z + b.z;
    y.w += a.w + b.w;
    ((float4*)out)[i4] = y;
}

// ---------------------------------------------------------------------------
extern "C" void kernel_launch(void* const* d_in, const int* in_sizes, int n_in,
                              void* d_out, int out_size) {
    const float* x   = (const float*)d_in[0];
    const int*   ei  = (const int*)d_in[1];
    const float* W1l = (const float*)d_in[2];
    const float* b1l = (const float*)d_in[3];
    const float* W1r = (const float*)d_in[4];
    const float* W2l = (const float*)d_in[5];
    const float* b2l = (const float*)d_in[6];
    const float* W2r = (const float*)d_in[7];
    float* out = (float*)d_out;

    float *agg, *hl;
    int *cnt;
    cudaGetSymbolAddress((void**)&agg, g_agg);
    cudaGetSymbolAddress((void**)&hl,  g_hl);
    cudaGetSymbolAddress((void**)&cnt, g_cnt);

    const int SMEM1 = (16384 + 64 * NP + 128) * 4;   // 99840 B
    const int SMEM2 = (16384 + 64 * NP) * 4;         // 99328 B
    cudaFuncSetAttribute(layer1_kernel, cudaFuncAttributeMaxDynamicSharedMemorySize, SMEM1);
    cudaFuncSetAttribute(gemm2_kernel,  cudaFuncAttributeMaxDynamicSharedMemorySize, SMEM2);

    const int NT = (N_NODES + 63) / 64;              // 1563

    // CSR build (once; shared by both layers)
    zero_kernel<<<(N_NODES / 4 + 255) / 256, 256>>>((float*)cnt, N_NODES / 4);
    hist_kernel<<<(N_EDGES + 255) / 256, 256>>>(ei);
    scan1_kernel<<<N_SCANB, 256>>>();
    scan2_kernel<<<1, 128>>>();
    scan3_kernel<<<(N_NODES + 255) / 256, 256>>>();
    fill_kernel<<<(N_EDGES + 255) / 256, 256>>>(ei);

    // Layer 1
    gather_kernel<<<(N_NODES * 32 + 255) / 256, 256>>>(x, agg);
    layer1_kernel<<<NT, 256, SMEM1>>>(x, W1l, b1l, W1r);

    // Layer 2: GEMM first (linearity), gather 64-dim hl, epilogue
    gemm2_kernel<<<NT, 256, SMEM2>>>(W2l, W2r, out);
    gather_kernel<<<(N_NODES * 32 + 255) / 256, 256>>>(hl, agg);
    final_kernel<<<(N_NODES * FEAT / 4 + 255) / 256, 256>>>(out, b2l);
}

// round 7
// speedup vs baseline: 5.3625x; 1.5185x over previous
#include <cuda_runtime.h>
#include <cstdint>

#define N_NODES 100000
#define FEAT 64
#define HID 128
#define N_EDGES 1200000
#define SCAN_B 1024
#define N_SCANB 98
#define NT ((N_NODES + 127) / 128)   // 782 tiles of 128 nodes
#define PA 132                       // padded row stride (floats) — conflict-free frags

// Scratch (device globals — no allocation allowed)
__device__ float g_agg[N_NODES * FEAT];
__device__ float g_h[N_NODES * HID];
__device__ float g_hl[N_NODES * FEAT];
__device__ float g_invdeg[N_NODES];
__device__ int   g_cnt[N_NODES];
__device__ int   g_rowptr[N_NODES];
__device__ int   g_cursor[N_NODES];
__device__ int   g_csr[N_EDGES];
__device__ int   g_bsum[N_SCANB];
__device__ int   g_boff[N_SCANB];

// ---------------------------------------------------------------------------
__device__ __forceinline__ float tf32r(float f) {
    uint32_t r;
    asm("cvt.rna.tf32.f32 %0, %1;" : "=r"(r) : "f"(f));
    return __uint_as_float(r);
}
__device__ __forceinline__ float4 tf32r4(float4 v) {
    return make_float4(tf32r(v.x), tf32r(v.y), tf32r(v.z), tf32r(v.w));
}
// d += A(16x8,row) * B(8x8,col)   (tf32 operands as b32, fp32 accum)
__device__ __forceinline__ void mma_tf32(float* d, const uint32_t* a, const uint32_t* b) {
    asm volatile(
        "mma.sync.aligned.m16n8k8.row.col.f32.tf32.tf32.f32 "
        "{%0,%1,%2,%3}, {%4,%5,%6,%7}, {%8,%9}, {%0,%1,%2,%3};"
        : "+f"(d[0]), "+f"(d[1]), "+f"(d[2]), "+f"(d[3])
        : "r"(a[0]), "r"(a[1]), "r"(a[2]), "r"(a[3]), "r"(b[0]), "r"(b[1]));
}

// ---------------------------------------------------------------------------
__global__ void zero_kernel(float* p, int n4) {
    int i = blockIdx.x * blockDim.x + threadIdx.x;
    if (i < n4) ((float4*)p)[i] = make_float4(0.f, 0.f, 0.f, 0.f);
}

// --------------------------- CSR build ------------------------------------
__global__ void hist_kernel(const int* __restrict__ ei) {
    int e = blockIdx.x * blockDim.x + threadIdx.x;
    if (e < N_EDGES) atomicAdd(&g_cnt[ei[N_EDGES + e]], 1);
}

__global__ void scan1_kernel() {
    __shared__ int ws[8];
    int b = blockIdx.x, t = threadIdx.x;
    int base = b * SCAN_B + t * 4;
    int c0 = (base + 0 < N_NODES) ? g_cnt[base + 0] : 0;
    int c1 = (base + 1 < N_NODES) ? g_cnt[base + 1] : 0;
    int c2 = (base + 2 < N_NODES) ? g_cnt[base + 2] : 0;
    int c3 = (base + 3 < N_NODES) ? g_cnt[base + 3] : 0;
    int s = c0 + c1 + c2 + c3;
    int lane = t & 31, w = t >> 5;
    int v = s;
    #pragma unroll
    for (int d = 1; d < 32; d <<= 1) {
        int u = __shfl_up_sync(~0u, v, d);
        if (lane >= d) v += u;
    }
    if (lane == 31) ws[w] = v;
    __syncthreads();
    if (t < 8) {
        int u = ws[t];
        #pragma unroll
        for (int d = 1; d < 8; d <<= 1) {
            int uu = __shfl_up_sync(0xffu, u, d);
            if (t >= d) u += uu;
        }
        ws[t] = u;
    }
    __syncthreads();
    int prefix = v - s + ((w > 0) ? ws[w - 1] : 0);
    int r0 = prefix, r1 = r0 + c0, r2 = r1 + c1, r3 = r2 + c2;
    if (base + 0 < N_NODES) g_rowptr[base + 0] = r0;
    if (base + 1 < N_NODES) g_rowptr[base + 1] = r1;
    if (base + 2 < N_NODES) g_rowptr[base + 2] = r2;
    if (base + 3 < N_NODES) g_rowptr[base + 3] = r3;
    if (t == 255) g_bsum[b] = ws[7];
}

__global__ void scan2_kernel() {
    __shared__ int s[128];
    int t = threadIdx.x;
    int v = (t < N_SCANB) ? g_bsum[t] : 0;
    s[t] = v;
    __syncthreads();
    #pragma unroll
    for (int d = 1; d < 128; d <<= 1) {
        int u = (t >= d) ? s[t - d] : 0;
        __syncthreads();
        s[t] += u;
        __syncthreads();
    }
    if (t < N_SCANB) g_boff[t] = s[t] - v;
}

__global__ void scan3_kernel() {
    int i = blockIdx.x * blockDim.x + threadIdx.x;
    if (i >= N_NODES) return;
    int r = g_rowptr[i] + g_boff[i / SCAN_B];
    g_rowptr[i] = r;
    g_cursor[i] = r;
    g_invdeg[i] = 1.0f / fmaxf((float)g_cnt[i], 1.0f);
}

__global__ void fill_kernel(const int* __restrict__ ei) {
    int e = blockIdx.x * blockDim.x + threadIdx.x;
    if (e >= N_EDGES) return;
    int src = ei[e];
    int dst = ei[N_EDGES + e];
    int pos = atomicAdd(&g_cursor[dst], 1);
    g_csr[pos] = src;
}

// --------------------------- Gather (mean) ---------------------------------
__global__ void gather_kernel(const float* __restrict__ vals,
                              float* __restrict__ aggm) {
    int gw = (blockIdx.x * blockDim.x + threadIdx.x) >> 5;
    if (gw >= N_NODES) return;
    int lane = threadIdx.x & 31;
    int start = g_rowptr[gw];
    int deg = g_cnt[gw];
    const float2* v2 = (const float2*)vals;
    float2 a0 = make_float2(0.f, 0.f), a1 = make_float2(0.f, 0.f);
    int i = 0;
    for (; i + 2 <= deg; i += 2) {
        int s0 = g_csr[start + i];
        int s1 = g_csr[start + i + 1];
        float2 u0 = v2[(size_t)s0 * 32 + lane];
        float2 u1 = v2[(size_t)s1 * 32 + lane];
        a0.x += u0.x; a0.y += u0.y;
        a1.x += u1.x; a1.y += u1.y;
    }
    if (i < deg) {
        int s0 = g_csr[start + i];
        float2 u0 = v2[(size_t)s0 * 32 + lane];
        a0.x += u0.x; a0.y += u0.y;
    }
    float inv = g_invdeg[gw];
    ((float2*)aggm)[(size_t)gw * 32 + lane] =
        make_float2((a0.x + a1.x) * inv, (a0.y + a1.y) * inv);
}

// --------------------------- tf32 mma.sync GEMM core ------------------------
// Tile: 128 nodes x 128 ch, k=128. 8 warps: wm = wid&3 (2 m16 tiles each),
// wn = wid>>2 (8 n8 tiles each). Fragments hand-loaded from padded smem.
struct FragCtx {
    int g, c, wm, wn;
};

__device__ __forceinline__ void gemm_core(const float* sA, const float* sB,
                                          float acc[2][8][4], FragCtx fc) {
    #pragma unroll
    for (int ks = 0; ks < 16; ks++) {
        int K = ks * 8;
        uint32_t af[2][4];
        #pragma unroll
        for (int mt = 0; mt < 2; mt++) {
            int R = fc.wm * 32 + mt * 16 + fc.g;
            const float* base = sA + R * PA + K + fc.c;
            af[mt][0] = __float_as_uint(base[0]);
            af[mt][1] = __float_as_uint(base[8 * PA]);
            af[mt][2] = __float_as_uint(base[4]);
            af[mt][3] = __float_as_uint(base[8 * PA + 4]);
        }
        uint32_t bf[8][2];
        #pragma unroll
        for (int nt = 0; nt < 8; nt++) {
            int N = fc.wn * 64 + nt * 8 + fc.g;
            const float* base = sB + N * PA + K + fc.c;
            bf[nt][0] = __float_as_uint(base[0]);
            bf[nt][1] = __float_as_uint(base[4]);
        }
        #pragma unroll
        for (int mt = 0; mt < 2; mt++)
            #pragma unroll
            for (int nt = 0; nt < 8; nt++)
                mma_tf32(acc[mt][nt], af[mt], bf[nt]);
    }
}

// --------------------------- Layer 1 GEMM -----------------------------------
// h = relu([aggm | x] @ [W1l|W1r]^T + b1l)
__global__ void __launch_bounds__(256, 1)
layer1_mma_kernel(const float* __restrict__ x,
                  const float* __restrict__ W1l,
                  const float* __restrict__ b1l,
                  const float* __restrict__ W1r) {
    extern __shared__ float sm[];
    float* sA = sm;                  // 128 * PA
    float* sB = sm + 128 * PA;       // 128 * PA
    float* sbias = sm + 2 * 128 * PA;

    int t = threadIdx.x;
    int wid = t >> 5, lane = t & 31;
    FragCtx fc{lane >> 2, lane & 3, wid & 3, wid >> 2};
    int n0 = blockIdx.x * 128;

    for (int i = t; i < 4096; i += 256) {
        int j = i >> 5, f4 = i & 31;
        int n = n0 + j;
        float4 v = make_float4(0.f, 0.f, 0.f, 0.f);
        if (n < N_NODES)
            v = (f4 < 16) ? ((const float4*)g_agg)[(size_t)n * 16 + f4]
                          : ((const float4*)x)[(size_t)n * 16 + (f4 - 16)];
        *(float4*)&sA[j * PA + f4 * 4] = tf32r4(v);
    }
    for (int i = t; i < 4096; i += 256) {
        int ch = i >> 5, f4 = i & 31;
        float4 w = (f4 < 16) ? ((const float4*)W1l)[ch * 16 + f4]
                             : ((const float4*)W1r)[ch * 16 + (f4 - 16)];
        *(float4*)&sB[ch * PA + f4 * 4] = tf32r4(w);
    }
    if (t < 128) sbias[t] = b1l[t];
    __syncthreads();

    float acc[2][8][4];
    #pragma unroll
    for (int mt = 0; mt < 2; mt++)
        #pragma unroll
        for (int nt = 0; nt < 8; nt++)
            #pragma unroll
            for (int k = 0; k < 4; k++) acc[mt][nt][k] = 0.0f;

    gemm_core(sA, sB, acc, fc);

    // epilogue: bias + relu -> g_h
    #pragma unroll
    for (int mt = 0; mt < 2; mt++) {
        int r0 = n0 + fc.wm * 32 + mt * 16 + fc.g;
        #pragma unroll
        for (int nt = 0; nt < 8; nt++) {
            int col = fc.wn * 64 + nt * 8 + fc.c * 2;
            float bx = sbias[col], by = sbias[col + 1];
            if (r0 < N_NODES) {
                float2 o = make_float2(fmaxf(acc[mt][nt][0] + bx, 0.f),
                                       fmaxf(acc[mt][nt][1] + by, 0.f));
                *(float2*)&g_h[(size_t)r0 * HID + col] = o;
            }
            if (r0 + 8 < N_NODES) {
                float2 o = make_float2(fmaxf(acc[mt][nt][2] + bx, 0.f),
                                       fmaxf(acc[mt][nt][3] + by, 0.f));
                *(float2*)&g_h[(size_t)(r0 + 8) * HID + col] = o;
            }
        }
    }
}

// --------------------------- Layer 2 GEMM -----------------------------------
// cols 0..63 (wn=0) -> g_hl = h @ W2l^T ; cols 64..127 (wn=1) -> out = h @ W2r^T
__global__ void __launch_bounds__(256, 1)
gemm2_mma_kernel(const float* __restrict__ W2l,
                 const float* __restrict__ W2r,
                 float* __restrict__ out) {
    extern __shared__ float sm[];
    float* sA = sm;
    float* sB = sm + 128 * PA;

    int t = threadIdx.x;
    int wid = t >> 5, lane = t & 31;
    FragCtx fc{lane >> 2, lane & 3, wid & 3, wid >> 2};
    int n0 = blockIdx.x * 128;

    for (int i = t; i < 4096; i += 256) {
        int j = i >> 5, f4 = i & 31;
        int n = n0 + j;
        float4 v = make_float4(0.f, 0.f, 0.f, 0.f);
        if (n < N_NODES) v = ((const float4*)g_h)[(size_t)n * 32 + f4];
        *(float4*)&sA[j * PA + f4 * 4] = tf32r4(v);
    }
    for (int i = t; i < 4096; i += 256) {
        int ch = i >> 5, f4 = i & 31;
        float4 w = (ch < 64) ? ((const float4*)W2l)[ch * 32 + f4]
                             : ((const float4*)W2r)[(ch - 64) * 32 + f4];
        *(float4*)&sB[ch * PA + f4 * 4] = tf32r4(w);
    }
    __syncthreads();

    float acc[2][8][4];
    #pragma unroll
    for (int mt = 0; mt < 2; mt++)
        #pragma unroll
        for (int nt = 0; nt < 8; nt++)
            #pragma unroll
            for (int k = 0; k < 4; k++) acc[mt][nt][k] = 0.0f;

    gemm_core(sA, sB, acc, fc);

    float* dst = (fc.wn == 0) ? g_hl : out;
    int cbase = (fc.wn == 0) ? 0 : 64;
    #pragma unroll
    for (int mt = 0; mt < 2; mt++) {
        int r0 = n0 + fc.wm * 32 + mt * 16 + fc.g;
        #pragma unroll
        for (int nt = 0; nt < 8; nt++) {
            int col = fc.wn * 64 + nt * 8 + fc.c * 2 - cbase;
            if (r0 < N_NODES)
                *(float2*)&dst[(size_t)r0 * FEAT + col] =
                    make_float2(acc[mt][nt][0], acc[mt][nt][1]);
            if (r0 + 8 < N_NODES)
                *(float2*)&dst[(size_t)(r0 + 8) * FEAT + col] =
                    make_float2(acc[mt][nt][2], acc[mt][nt][3]);
        }
    }
}

// --------------------------- Final epilogue ---------------------------------
__global__ void final_kernel(float* __restrict__ out,
                             const float* __restrict__ b2l) {
    int i4 = blockIdx.x * blockDim.x + threadIdx.x;
    if (i4 >= N_NODES * FEAT / 4) return;
    int o4 = i4 & 15;
    float4 a = ((const float4*)g_agg)[i4];
    float4 b = ((const float4*)b2l)[o4];
    float4 y = ((float4*)out)[i4];
    y.x += a.x + b.x;
    y.y += a.y + b.y;
    y.z += a.z + b.z;
    y.w += a.w + b.w;
    ((float4*)out)[i4] = y;
}

// ---------------------------------------------------------------------------
extern "C" void kernel_launch(void* const* d_in, const int* in_sizes, int n_in,
                              void* d_out, int out_size) {
    const float* x   = (const float*)d_in[0];
    const int*   ei  = (const int*)d_in[1];
    const float* W1l = (const float*)d_in[2];
    const float* b1l = (const float*)d_in[3];
    const float* W1r = (const float*)d_in[4];
    const float* W2l = (const float*)d_in[5];
    const float* b2l = (const float*)d_in[6];
    const float* W2r = (const float*)d_in[7];
    float* out = (float*)d_out;

    float *agg, *hl;
    int *cnt;
    cudaGetSymbolAddress((void**)&agg, g_agg);
    cudaGetSymbolAddress((void**)&hl,  g_hl);
    cudaGetSymbolAddress((void**)&cnt, g_cnt);

    const int SMEMG = (2 * 128 * PA + 128) * 4;   // 135680 B
    cudaFuncSetAttribute(layer1_mma_kernel, cudaFuncAttributeMaxDynamicSharedMemorySize, SMEMG);
    cudaFuncSetAttribute(gemm2_mma_kernel,  cudaFuncAttributeMaxDynamicSharedMemorySize, SMEMG);

    // CSR build (shared by both layers)
    zero_kernel<<<(N_NODES / 4 + 255) / 256, 256>>>((float*)cnt, N_NODES / 4);
    hist_kernel<<<(N_EDGES + 255) / 256, 256>>>(ei);
    scan1_kernel<<<N_SCANB, 256>>>();
    scan2_kernel<<<1, 128>>>();
    scan3_kernel<<<(N_NODES + 255) / 256, 256>>>();
    fill_kernel<<<(N_EDGES + 255) / 256, 256>>>(ei);

    // Layer 1
    gather_kernel<<<(N_NODES * 32 + 255) / 256, 256>>>(x, agg);
    layer1_mma_kernel<<<NT, 256, SMEMG>>>(x, W1l, b1l, W1r);

    // Layer 2: GEMM first (linearity), gather 64-dim hl, epilogue
    gemm2_mma_kernel<<<NT, 256, SMEMG>>>(W2l, W2r, out);
    gather_kernel<<<(N_NODES * 32 + 255) / 256, 256>>>(hl, agg);
    final_kernel<<<(N_NODES * FEAT / 4 + 255) / 256, 256>>>(out, b2l);
}

// round 8
// speedup vs baseline: 6.0646x; 1.1309x over previous
#include <cuda_runtime.h>
#include <cstdint>

#define N_NODES 100000
#define FEAT 64
#define HID 128
#define N_EDGES 1200000
#define SCAN_B 1024
#define N_SCANB 98
#define NT64 ((N_NODES + 63) / 64)   // 1563 tiles of 64 nodes
#define PA 132                       // padded row stride (floats)

// Scratch (device globals — no allocation allowed)
__device__ float g_agg[N_NODES * FEAT];
__device__ float g_h[N_NODES * HID];
__device__ float g_hl[N_NODES * FEAT];
__device__ float g_invdeg[N_NODES];
__device__ int   g_cnt[N_NODES];
__device__ int   g_rowptr[N_NODES];
__device__ int   g_cursor[N_NODES];
__device__ int   g_csr[N_EDGES];
__device__ int   g_bsum[N_SCANB];

// ---------------------------------------------------------------------------
__device__ __forceinline__ float tf32r(float f) {
    uint32_t r;
    asm("cvt.rna.tf32.f32 %0, %1;" : "=r"(r) : "f"(f));
    return __uint_as_float(r);
}
__device__ __forceinline__ float4 tf32r4(float4 v) {
    return make_float4(tf32r(v.x), tf32r(v.y), tf32r(v.z), tf32r(v.w));
}
__device__ __forceinline__ void mma_tf32(float* d, const uint32_t* a, const uint32_t* b) {
    asm volatile(
        "mma.sync.aligned.m16n8k8.row.col.f32.tf32.tf32.f32 "
        "{%0,%1,%2,%3}, {%4,%5,%6,%7}, {%8,%9}, {%0,%1,%2,%3};"
        : "+f"(d[0]), "+f"(d[1]), "+f"(d[2]), "+f"(d[3])
        : "r"(a[0]), "r"(a[1]), "r"(a[2]), "r"(a[3]), "r"(b[0]), "r"(b[1]));
}

// ---------------------------------------------------------------------------
__global__ void zero_kernel(float* p, int n4) {
    int i = blockIdx.x * blockDim.x + threadIdx.x;
    if (i < n4) ((float4*)p)[i] = make_float4(0.f, 0.f, 0.f, 0.f);
}

// --------------------------- CSR build ------------------------------------
__global__ void hist_kernel(const int* __restrict__ ei) {
    int e = blockIdx.x * blockDim.x + threadIdx.x;
    if (e < N_EDGES) atomicAdd(&g_cnt[ei[N_EDGES + e]], 1);
}

__global__ void scan1_kernel() {
    __shared__ int ws[8];
    int b = blockIdx.x, t = threadIdx.x;
    int base = b * SCAN_B + t * 4;
    int c0 = (base + 0 < N_NODES) ? g_cnt[base + 0] : 0;
    int c1 = (base + 1 < N_NODES) ? g_cnt[base + 1] : 0;
    int c2 = (base + 2 < N_NODES) ? g_cnt[base + 2] : 0;
    int c3 = (base + 3 < N_NODES) ? g_cnt[base + 3] : 0;
    int s = c0 + c1 + c2 + c3;
    int lane = t & 31, w = t >> 5;
    int v = s;
    #pragma unroll
    for (int d = 1; d < 32; d <<= 1) {
        int u = __shfl_up_sync(~0u, v, d);
        if (lane >= d) v += u;
    }
    if (lane == 31) ws[w] = v;
    __syncthreads();
    if (t < 8) {
        int u = ws[t];
        #pragma unroll
        for (int d = 1; d < 8; d <<= 1) {
            int uu = __shfl_up_sync(0xffu, u, d);
            if (t >= d) u += uu;
        }
        ws[t] = u;
    }
    __syncthreads();
    int prefix = v - s + ((w > 0) ? ws[w - 1] : 0);
    int r0 = prefix, r1 = r0 + c0, r2 = r1 + c1, r3 = r2 + c2;
    if (base + 0 < N_NODES) g_rowptr[base + 0] = r0;
    if (base + 1 < N_NODES) g_rowptr[base + 1] = r1;
    if (base + 2 < N_NODES) g_rowptr[base + 2] = r2;
    if (base + 3 < N_NODES) g_rowptr[base + 3] = r3;
    if (t == 255) g_bsum[b] = ws[7];
}

// scan3: each 256-node block lies in ONE scan superblock; reduce bsums below it.
__global__ void scan3_kernel() {
    __shared__ int red[256];
    __shared__ int off;
    int t = threadIdx.x;
    int sb = (blockIdx.x * 256) / SCAN_B;     // superblock index (constant per block)
    int partial = 0;
    for (int i = t; i < sb; i += 256) partial += g_bsum[i];
    red[t] = partial;
    __syncthreads();
    #pragma unroll
    for (int d = 128; d > 0; d >>= 1) {
        if (t < d) red[t] += red[t + d];
        __syncthreads();
    }
    if (t == 0) off = red[0];
    __syncthreads();
    int i = blockIdx.x * 256 + t;
    if (i >= N_NODES) return;
    int r = g_rowptr[i] + off;
    g_rowptr[i] = r;
    g_cursor[i] = r;
    g_invdeg[i] = 1.0f / fmaxf((float)g_cnt[i], 1.0f);
}

__global__ void fill_kernel(const int* __restrict__ ei) {
    int e = blockIdx.x * blockDim.x + threadIdx.x;
    if (e >= N_EDGES) return;
    int src = ei[e];
    int dst = ei[N_EDGES + e];
    int pos = atomicAdd(&g_cursor[dst], 1);
    g_csr[pos] = src;
}

// --------------------------- Gather 1 (x -> agg, mean) ----------------------
__global__ void gather_kernel(const float* __restrict__ vals,
                              float* __restrict__ aggm) {
    int gw = (blockIdx.x * blockDim.x + threadIdx.x) >> 5;
    if (gw >= N_NODES) return;
    int lane = threadIdx.x & 31;
    int start = g_rowptr[gw];
    int deg = g_cnt[gw];
    const float2* v2 = (const float2*)vals;
    float2 a0 = make_float2(0.f, 0.f), a1 = make_float2(0.f, 0.f);
    int i = 0;
    for (; i + 2 <= deg; i += 2) {
        int s0 = g_csr[start + i];
        int s1 = g_csr[start + i + 1];
        float2 u0 = v2[(size_t)s0 * 32 + lane];
        float2 u1 = v2[(size_t)s1 * 32 + lane];
        a0.x += u0.x; a0.y += u0.y;
        a1.x += u1.x; a1.y += u1.y;
    }
    if (i < deg) {
        int s0 = g_csr[start + i];
        float2 u0 = v2[(size_t)s0 * 32 + lane];
        a0.x += u0.x; a0.y += u0.y;
    }
    float inv = g_invdeg[gw];
    ((float2*)aggm)[(size_t)gw * 32 + lane] =
        make_float2((a0.x + a1.x) * inv, (a0.y + a1.y) * inv);
}

// ------------------- Gather 2 fused with final epilogue ---------------------
// out[n] += mean_gather(hl)[n] + b2l    (read-modify-write on out)
__global__ void gather2_final_kernel(const float* __restrict__ hl,
                                     const float* __restrict__ b2l,
                                     float* __restrict__ out) {
    int gw = (blockIdx.x * blockDim.x + threadIdx.x) >> 5;
    if (gw >= N_NODES) return;
    int lane = threadIdx.x & 31;
    int start = g_rowptr[gw];
    int deg = g_cnt[gw];
    const float2* v2 = (const float2*)hl;
    float2 a0 = make_float2(0.f, 0.f), a1 = make_float2(0.f, 0.f);
    int i = 0;
    for (; i + 2 <= deg; i += 2) {
        int s0 = g_csr[start + i];
        int s1 = g_csr[start + i + 1];
        float2 u0 = v2[(size_t)s0 * 32 + lane];
        float2 u1 = v2[(size_t)s1 * 32 + lane];
        a0.x += u0.x; a0.y += u0.y;
        a1.x += u1.x; a1.y += u1.y;
    }
    if (i < deg) {
        int s0 = g_csr[start + i];
        float2 u0 = v2[(size_t)s0 * 32 + lane];
        a0.x += u0.x; a0.y += u0.y;
    }
    float inv = g_invdeg[gw];
    float2 b = ((const float2*)b2l)[lane];
    float2* op = (float2*)out + (size_t)gw * 32 + lane;
    float2 y = *op;
    y.x += (a0.x + a1.x) * inv + b.x;
    y.y += (a0.y + a1.y) * inv + b.y;
    *op = y;
}

// --------------------------- tf32 mma.sync GEMM core ------------------------
// Tile: 64 nodes x 128 ch, k=128, 2 CTAs/SM. 8 warps: wm=wid&3 (one m16 tile),
// wn=wid>>2 (8 n8 tiles). g=lane>>2, c=lane&3.
__device__ __forceinline__ void gemm_core64(const float* sA, const float* sB,
                                            float acc[8][4],
                                            int g, int c, int wm, int wn) {
    #pragma unroll
    for (int ks = 0; ks < 16; ks++) {
        int K = ks * 8;
        uint32_t af[4];
        {
            const float* base = sA + (wm * 16 + g) * PA + K + c;
            af[0] = __float_as_uint(base[0]);
            af[1] = __float_as_uint(base[8 * PA]);
            af[2] = __float_as_uint(base[4]);
            af[3] = __float_as_uint(base[8 * PA + 4]);
        }
        uint32_t bf[8][2];
        #pragma unroll
        for (int nt = 0; nt < 8; nt++) {
            const float* base = sB + (wn * 64 + nt * 8 + g) * PA + K + c;
            bf[nt][0] = __float_as_uint(base[0]);
            bf[nt][1] = __float_as_uint(base[4]);
        }
        #pragma unroll
        for (int nt = 0; nt < 8; nt++)
            mma_tf32(acc[nt], af, bf[nt]);
    }
}

// --------------------------- Layer 1 GEMM -----------------------------------
__global__ void __launch_bounds__(256, 2)
layer1_mma_kernel(const float* __restrict__ x,
                  const float* __restrict__ W1l,
                  const float* __restrict__ b1l,
                  const float* __restrict__ W1r) {
    extern __shared__ float sm[];
    float* sA = sm;                        // 64 * PA
    float* sB = sm + 64 * PA;              // 128 * PA
    float* sbias = sm + 64 * PA + 128 * PA;

    int t = threadIdx.x;
    int wid = t >> 5, lane = t & 31;
    int g = lane >> 2, c = lane & 3, wm = wid & 3, wn = wid >> 2;
    int n0 = blockIdx.x * 64;

    for (int i = t; i < 2048; i += 256) {         // A: 64 nodes x 32 float4
        int j = i >> 5, f4 = i & 31;
        int n = n0 + j;
        float4 v = make_float4(0.f, 0.f, 0.f, 0.f);
        if (n < N_NODES)
            v = (f4 < 16) ? ((const float4*)g_agg)[(size_t)n * 16 + f4]
                          : ((const float4*)x)[(size_t)n * 16 + (f4 - 16)];
        *(float4*)&sA[j * PA + f4 * 4] = tf32r4(v);
    }
    for (int i = t; i < 4096; i += 256) {         // B: 128 ch x 32 float4
        int ch = i >> 5, f4 = i & 31;
        float4 w = (f4 < 16) ? ((const float4*)W1l)[ch * 16 + f4]
                             : ((const float4*)W1r)[ch * 16 + (f4 - 16)];
        *(float4*)&sB[ch * PA + f4 * 4] = tf32r4(w);
    }
    if (t < 128) sbias[t] = b1l[t];
    __syncthreads();

    float acc[8][4];
    #pragma unroll
    for (int nt = 0; nt < 8; nt++)
        #pragma unroll
        for (int k = 0; k < 4; k++) acc[nt][k] = 0.0f;

    gemm_core64(sA, sB, acc, g, c, wm, wn);

    int r0 = n0 + wm * 16 + g;
    #pragma unroll
    for (int nt = 0; nt < 8; nt++) {
        int col = wn * 64 + nt * 8 + c * 2;
        float bx = sbias[col], by = sbias[col + 1];
        if (r0 < N_NODES)
            *(float2*)&g_h[(size_t)r0 * HID + col] =
                make_float2(fmaxf(acc[nt][0] + bx, 0.f), fmaxf(acc[nt][1] + by, 0.f));
        if (r0 + 8 < N_NODES)
            *(float2*)&g_h[(size_t)(r0 + 8) * HID + col] =
                make_float2(fmaxf(acc[nt][2] + bx, 0.f), fmaxf(acc[nt][3] + by, 0.f));
    }
}

// --------------------------- Layer 2 GEMM -----------------------------------
__global__ void __launch_bounds__(256, 2)
gemm2_mma_kernel(const float* __restrict__ W2l,
                 const float* __restrict__ W2r,
                 float* __restrict__ out) {
    extern __shared__ float sm[];
    float* sA = sm;
    float* sB = sm + 64 * PA;

    int t = threadIdx.x;
    int wid = t >> 5, lane = t & 31;
    int g = lane >> 2, c = lane & 3, wm = wid & 3, wn = wid >> 2;
    int n0 = blockIdx.x * 64;

    for (int i = t; i < 2048; i += 256) {
        int j = i >> 5, f4 = i & 31;
        int n = n0 + j;
        float4 v = make_float4(0.f, 0.f, 0.f, 0.f);
        if (n < N_NODES) v = ((const float4*)g_h)[(size_t)n * 32 + f4];
        *(float4*)&sA[j * PA + f4 * 4] = tf32r4(v);
    }
    for (int i = t; i < 4096; i += 256) {
        int ch = i >> 5, f4 = i & 31;
        float4 w = (ch < 64) ? ((const float4*)W2l)[ch * 32 + f4]
                             : ((const float4*)W2r)[(ch - 64) * 32 + f4];
        *(float4*)&sB[ch * PA + f4 * 4] = tf32r4(w);
    }
    __syncthreads();

    float acc[8][4];
    #pragma unroll
    for (int nt = 0; nt < 8; nt++)
        #pragma unroll
        for (int k = 0; k < 4; k++) acc[nt][k] = 0.0f;

    gemm_core64(sA, sB, acc, g, c, wm, wn);

    float* dst = (wn == 0) ? g_hl : out;
    int cbase = (wn == 0) ? 0 : 64;
    int r0 = n0 + wm * 16 + g;
    #pragma unroll
    for (int nt = 0; nt < 8; nt++) {
        int col = wn * 64 + nt * 8 + c * 2 - cbase;
        if (r0 < N_NODES)
            *(float2*)&dst[(size_t)r0 * FEAT + col] = make_float2(acc[nt][0], acc[nt][1]);
        if (r0 + 8 < N_NODES)
            *(float2*)&dst[(size_t)(r0 + 8) * FEAT + col] = make_float2(acc[nt][2], acc[nt][3]);
    }
}

// ---------------------------------------------------------------------------
extern "C" void kernel_launch(void* const* d_in, const int* in_sizes, int n_in,
                              void* d_out, int out_size) {
    const float* x   = (const float*)d_in[0];
    const int*   ei  = (const int*)d_in[1];
    const float* W1l = (const float*)d_in[2];
    const float* b1l = (const float*)d_in[3];
    const float* W1r = (const float*)d_in[4];
    const float* W2l = (const float*)d_in[5];
    const float* b2l = (const float*)d_in[6];
    const float* W2r = (const float*)d_in[7];
    float* out = (float*)d_out;

    float *agg, *hl;
    int *cnt;
    cudaGetSymbolAddress((void**)&agg, g_agg);
    cudaGetSymbolAddress((void**)&hl,  g_hl);
    cudaGetSymbolAddress((void**)&cnt, g_cnt);

    const int SMEM1 = (64 * PA + 128 * PA + 128) * 4;   // 101,888 B
    const int SMEM2 = (64 * PA + 128 * PA) * 4;         // 101,376 B
    cudaFuncSetAttribute(layer1_mma_kernel, cudaFuncAttributeMaxDynamicSharedMemorySize, SMEM1);
    cudaFuncSetAttribute(gemm2_mma_kernel,  cudaFuncAttributeMaxDynamicSharedMemorySize, SMEM2);

    // CSR build
    zero_kernel<<<(N_NODES / 4 + 255) / 256, 256>>>((float*)cnt, N_NODES / 4);
    hist_kernel<<<(N_EDGES + 255) / 256, 256>>>(ei);
    scan1_kernel<<<N_SCANB, 256>>>();
    scan3_kernel<<<(N_NODES + 255) / 256, 256>>>();
    fill_kernel<<<(N_EDGES + 255) / 256, 256>>>(ei);

    // Layer 1
    gather_kernel<<<(N_NODES * 32 + 255) / 256, 256>>>(x, agg);
    layer1_mma_kernel<<<NT64, 256, SMEM1>>>(x, W1l, b1l, W1r);

    // Layer 2
    gemm2_mma_kernel<<<NT64, 256, SMEM2>>>(W2l, W2r, out);
    gather2_final_kernel<<<(N_NODES * 32 + 255) / 256, 256>>>(hl, b2l, out);
}